// round 7
// baseline (speedup 1.0000x reference)
#include <cuda_runtime.h>
#include <cuda_bf16.h>
#include <math_constants.h>

// Problem constants (fixed by the dataset):
//   N = 55440*1024 = 56,770,560 fp32; candidates L in [4,32] dividing N -> 20
//   P = lcm(candidates) = 110880, N / P = 512
#define NTOT   56770560
#define PP4    27720        // P/4 float4 positions per period
#define RSPLIT 8            // split the 512 repeats 8 ways
#define RCHUNK 64           // 512 / RSPLIT
#define NCAND  20
#define NBX    55           // ceil(PP4 / 512); block front = 512 f4 = 8KB
#define NBLK   (NBX * RSPLIT)   // 440 blocks = single uniform wave @3/SM (444)

// Scratch (__device__ globals; plain per-block stores -> no init required)
__device__ unsigned g_blk[NBLK][NCAND];  // per-block candidate maxima (float bits)
__device__ unsigned g_done;             // completion counter, self-resets to 0

// ---------------------------------------------------------------------------
// Single fused kernel. 8KB-contiguous block fronts:
//   thread owns f4 positions t0 = bx*512 + tid and t1 = t0 + 256; per r-step
//   the block's 16 warp-loads cover a contiguous 8KB span; r strides by the
//   period (PP4 f4s). 440 fronts advance in parallel (99% uniform one-wave).
// Phase B: evaluate all 20 candidates on chunk-local (mn, mx). Valid since
//   max over (p,r) = max over chunks of per-chunk candidate max, and
//   max_v |fl(v-c)| = max(fl(mx-c), fl(c-mn)) exactly (fl monotone,
//   sign-symmetric). pat = x[p % L], L literal after unroll.
// Phase C: shfl-butterfly warp reduce -> lane-0 shared atomics -> per-block
//   store to g_blk; fenced last-done block reduces, scores, argmax, writes
//   the 42 outputs. Counter self-resets for graph replay.
// ---------------------------------------------------------------------------
__global__ __launch_bounds__(256, 3) void pm_fused(const float4* __restrict__ x4,
                                                   float* __restrict__ out,
                                                   int out_size) {
    __shared__ float    s_pat[32];
    __shared__ unsigned s_max[NCAND];
    __shared__ bool     s_last;

    const int LENS[NCAND] = {4,5,6,7,8,9,10,11,12,14,15,16,18,20,21,22,24,28,30,32};

    int  t0 = blockIdx.x * 512 + threadIdx.x;
    int  t1 = t0 + 256;
    bool v0 = (t0 < PP4);
    bool v1 = (t1 < PP4);

    // --- Phase A first: no barrier between kernel entry and first LDG ---
    float4 mn0 = make_float4( CUDART_INF_F,  CUDART_INF_F,  CUDART_INF_F,  CUDART_INF_F);
    float4 mx0 = make_float4(-CUDART_INF_F, -CUDART_INF_F, -CUDART_INF_F, -CUDART_INF_F);
    float4 mn1 = mn0, mx1 = mx0;

    {
        const float4* base = x4 + (size_t)blockIdx.y * (RCHUNK * PP4);
#pragma unroll 4
        for (int r = 0; r < RCHUNK; r++) {
            const float4* row = base + (size_t)r * PP4;
            if (v0) {
                float4 u = __ldcs(row + t0);
                mn0.x = fminf(mn0.x, u.x); mx0.x = fmaxf(mx0.x, u.x);
                mn0.y = fminf(mn0.y, u.y); mx0.y = fmaxf(mx0.y, u.y);
                mn0.z = fminf(mn0.z, u.z); mx0.z = fmaxf(mx0.z, u.z);
                mn0.w = fminf(mn0.w, u.w); mx0.w = fmaxf(mx0.w, u.w);
            }
            if (v1) {
                float4 u = __ldcs(row + t1);
                mn1.x = fminf(mn1.x, u.x); mx1.x = fmaxf(mx1.x, u.x);
                mn1.y = fminf(mn1.y, u.y); mx1.y = fmaxf(mx1.y, u.y);
                mn1.z = fminf(mn1.z, u.z); mx1.z = fmaxf(mx1.z, u.z);
                mn1.w = fminf(mn1.w, u.w); mx1.w = fmaxf(mx1.w, u.w);
            }
        }
    }

    // Pattern + reduction smem init (off the load critical path)
    if (threadIdx.x < 32)    s_pat[threadIdx.x] = ((const float*)x4)[threadIdx.x];
    if (threadIdx.x < NCAND) s_max[threadIdx.x] = 0u;
    __syncthreads();

    // --- Phase B: 20-candidate fold on this thread's 8 scalar positions ---
    float acc[NCAND];
#pragma unroll
    for (int k = 0; k < NCAND; k++) acc[k] = 0.0f;

    if (v0) {
        float mnk[4] = {mn0.x, mn0.y, mn0.z, mn0.w};
        float mxk[4] = {mx0.x, mx0.y, mx0.z, mx0.w};
        int p0 = 4 * t0;
#pragma unroll
        for (int j = 0; j < 4; j++) {
            int pp = p0 + j;
#pragma unroll
            for (int k = 0; k < NCAND; k++) {
                int   L   = LENS[k];                 // literal after unroll
                float ctr = s_pat[pp % L];
                float d   = fmaxf(mxk[j] - ctr, ctr - mnk[j]);
                acc[k]    = fmaxf(acc[k], d);
            }
        }
    }
    if (v1) {
        float mnk[4] = {mn1.x, mn1.y, mn1.z, mn1.w};
        float mxk[4] = {mx1.x, mx1.y, mx1.z, mx1.w};
        int p0 = 4 * t1;
#pragma unroll
        for (int j = 0; j < 4; j++) {
            int pp = p0 + j;
#pragma unroll
            for (int k = 0; k < NCAND; k++) {
                int   L   = LENS[k];
                float ctr = s_pat[pp % L];
                float d   = fmaxf(mxk[j] - ctr, ctr - mnk[j]);
                acc[k]    = fmaxf(acc[k], d);
            }
        }
    }

    // --- Phase C: warp shfl reduce, lane-0 shared atomics, per-block store ---
#pragma unroll
    for (int k = 0; k < NCAND; k++) {
        float a = acc[k];
        a = fmaxf(a, __shfl_xor_sync(0xFFFFFFFFu, a, 16));
        a = fmaxf(a, __shfl_xor_sync(0xFFFFFFFFu, a, 8));
        a = fmaxf(a, __shfl_xor_sync(0xFFFFFFFFu, a, 4));
        a = fmaxf(a, __shfl_xor_sync(0xFFFFFFFFu, a, 2));
        a = fmaxf(a, __shfl_xor_sync(0xFFFFFFFFu, a, 1));
        acc[k] = a;
    }
    if ((threadIdx.x & 31) == 0) {
#pragma unroll
        for (int k = 0; k < NCAND; k++)
            atomicMax(&s_max[k], __float_as_uint(acc[k]));
    }
    __syncthreads();

    int bid = blockIdx.y * gridDim.x + blockIdx.x;
    if (threadIdx.x < NCAND)
        g_blk[bid][threadIdx.x] = s_max[threadIdx.x];

    __threadfence();   // publish g_blk before signaling completion
    if (threadIdx.x == 0) {
        unsigned prev = atomicAdd(&g_done, 1u);
        s_last = (prev == NBLK - 1);
    }
    __syncthreads();
    if (!s_last) return;

    // --- Finalize (one block): reduce g_blk, scores, argmax, outputs ---
    __threadfence();   // acquire all writers' g_blk stores
    __shared__ unsigned s_fin[NCAND];
    if (threadIdx.x == 0) g_done = 0u;            // reset for next replay
    if (threadIdx.x < NCAND) s_fin[threadIdx.x] = 0u;
    __syncthreads();

    if (threadIdx.x < 240) {                      // 12 groups x 20 candidates
        int g = threadIdx.x / NCAND;
        int k = threadIdx.x % NCAND;
        unsigned v = 0u;
        for (int b = g; b < NBLK; b += 12)
            v = max(v, g_blk[b][k]);
        atomicMax(&s_fin[k], v);
    }
    __syncthreads();

    if (threadIdx.x == 0) {
        float best = 0.0f;
        int   bidx = 0;
#pragma unroll
        for (int k = 0; k < NCAND; k++) {
            float md  = __uint_as_float(s_fin[k]);
            int   L   = LENS[k];
            float raw = (float)((double)(NTOT / L) / (double)L);
            float eff = (md < 0.01f) ? raw : 0.0f;
            if (k < out_size)      out[k]      = md;
            if (20 + k < out_size) out[20 + k] = eff;
            if (eff > best) { best = eff; bidx = k; }  // first max, like jnp.argmax
        }
        if (out_size > 40) out[40] = (float)bidx;
        if (out_size > 41) out[41] = best;
    }
}

// ---------------------------------------------------------------------------
extern "C" void kernel_launch(void* const* d_in, const int* in_sizes, int n_in,
                              void* d_out, int out_size) {
    const float* x = (const float*)d_in[0];
    float* out = (float*)d_out;

    dim3 grid(NBX, RSPLIT);
    pm_fused<<<grid, 256>>>((const float4*)x, out, out_size);
}